// round 16
// baseline (speedup 1.0000x reference)
#include <cuda_runtime.h>
#include <cuda_bf16.h>
#include <math_constants.h>
#include <stdint.h>

#define CCH   128
#define NH    4
#define HD    32
#define NPT   4096
#define EPSBN 1e-5f
#define KSPLIT 4
#define KEYS_PER_SPLIT (NPT / KSPLIT)   // 1024

// -------------------- scratch --------------------
__device__ float g_q[CCH * NPT];
__device__ float4 g_ktb_raw[NH * NPT * HD / 8];          // bf16 [head][key][dim]
__device__ float4 g_vb_raw[NH * HD * NPT / 8];           // bf16 [head][dim][key]
__device__ float g_po[KSPLIT * NH * HD * NPT];
__device__ float g_pl[KSPLIT * NH * NPT];
__device__ float g_attn[CCH * NPT];
__device__ float g_mh[CCH * NPT];
__device__ float g_h1[2 * CCH * NPT];
__device__ float g_h2[CCH * NPT];
__device__ float g_bnscale[2 * CCH];
__device__ float g_bnshift[2 * CCH];

// -------------------- ptx helpers --------------------
__device__ __forceinline__ float ex2f(float x) {
    float r; asm("ex2.approx.ftz.f32 %0, %1;" : "=f"(r) : "f"(x)); return r;
}
__device__ __forceinline__ uint32_t packbf(float lo, float hi) {
    uint32_t r; asm("cvt.rn.bf16x2.f32 %0, %1, %2;" : "=r"(r) : "f"(hi), "f"(lo)); return r;
}
__device__ __forceinline__ void mma_tf32(float& c0, float& c1, float& c2, float& c3,
                                         uint32_t a0, uint32_t a1, uint32_t a2, uint32_t a3,
                                         uint32_t b0, uint32_t b1) {
    asm volatile("mma.sync.aligned.m16n8k8.row.col.f32.tf32.tf32.f32 "
                 "{%0,%1,%2,%3}, {%4,%5,%6,%7}, {%8,%9}, {%0,%1,%2,%3};"
                 : "+f"(c0), "+f"(c1), "+f"(c2), "+f"(c3)
                 : "r"(a0), "r"(a1), "r"(a2), "r"(a3), "r"(b0), "r"(b1));
}
__device__ __forceinline__ void mma_bf16(float& c0, float& c1, float& c2, float& c3,
                                         uint32_t a0, uint32_t a1, uint32_t a2, uint32_t a3,
                                         uint32_t b0, uint32_t b1) {
    asm volatile("mma.sync.aligned.m16n8k16.row.col.f32.bf16.bf16.f32 "
                 "{%0,%1,%2,%3}, {%4,%5,%6,%7}, {%8,%9}, {%0,%1,%2,%3};"
                 : "+f"(c0), "+f"(c1), "+f"(c2), "+f"(c3)
                 : "r"(a0), "r"(a1), "r"(a2), "r"(a3), "r"(b0), "r"(b1));
}
__device__ __forceinline__ void ldsm4(uint32_t& r0, uint32_t& r1, uint32_t& r2, uint32_t& r3,
                                      uint32_t addr) {
    asm volatile("ldmatrix.sync.aligned.m8n8.x4.shared.b16 {%0,%1,%2,%3}, [%4];"
                 : "=r"(r0), "=r"(r1), "=r"(r2), "=r"(r3) : "r"(addr));
}
__device__ __forceinline__ void cpasync16(uint32_t dst, const void* src) {
    asm volatile("cp.async.cg.shared.global [%0], [%1], 16;" :: "r"(dst), "l"(src));
}
__device__ __forceinline__ void cpcommit() { asm volatile("cp.async.commit_group;"); }
template <int N> __device__ __forceinline__ void cpwait() {
    asm volatile("cp.async.wait_group %0;" :: "n"(N));
}

// ==================== tf32 MMA conv1x1, 4-stage pipelined ====================
// Optional BN apply+relu on X tiles (bnsc != null; channel = k row index).
#define CSTAGES 4

__global__ __launch_bounds__(128) void conv_mma_kernel(
    const float* __restrict__ W, const float* __restrict__ X,
    const float* __restrict__ X2, int CinX,
    const float* __restrict__ bias, void* __restrict__ Yout,
    int Cin, int Npts, int mode,
    const float* __restrict__ bnsc, const float* __restrict__ bnsh,
    const float* W1, const float* b1, void* Y1,
    const float* W2, const float* b2, void* Y2, int fused) {
    __shared__ __align__(16) float Ws[CSTAGES][64 * 20];
    __shared__ __align__(16) float Xs[CSTAGES][16 * 72];

    const int t = threadIdx.x;
    const int warp = t >> 5, lane = t & 31;
    const int l4 = lane >> 2, lm4 = lane & 3;
    int row0, by = blockIdx.y;
    if (fused) {
        int grp = by >> 1;
        row0 = (by & 1) * 64;
        if (grp == 1) { W = W1; bias = b1; Yout = Y1; mode = 1; }
        else if (grp == 2) { W = W2; bias = b2; Yout = Y2; mode = 2; }
    } else {
        row0 = by * 64;
    }
    const int col0 = blockIdx.x * 64;

    float acc[8][4];
#pragma unroll
    for (int i = 0; i < 8; i++)
#pragma unroll
        for (int j = 0; j < 4; j++) acc[i][j] = 0.f;

    uint32_t wb[CSTAGES], xb[CSTAGES];
#pragma unroll
    for (int s = 0; s < CSTAGES; s++) {
        wb[s] = (uint32_t)__cvta_generic_to_shared(Ws[s]);
        xb[s] = (uint32_t)__cvta_generic_to_shared(Xs[s]);
    }

    auto fill = [&](int buf, int k0) {
#pragma unroll
        for (int i = 0; i < 2; i++) {
            int idx = t + i * 128;
            int r = idx >> 2, c = idx & 3;
            cpasync16(wb[buf] + (r * 20 + c * 4) * 4, W + (size_t)(row0 + r) * Cin + k0 + c * 4);
        }
#pragma unroll
        for (int i = 0; i < 2; i++) {
            int idx = t + i * 128;
            int r = idx >> 4, c = idx & 15;
            int kr = k0 + r;
            const float* base = (kr < CinX) ? (X + (size_t)kr * Npts)
                                            : (X2 + (size_t)(kr - CinX) * Npts);
            cpasync16(xb[buf] + (r * 72 + c * 4) * 4, base + col0 + c * 4);
        }
    };

    const int KT = Cin >> 4;
#pragma unroll
    for (int p = 0; p < 3; p++) {
        fill(p, p * 16);
        cpcommit();
    }
    for (int kt = 0; kt < KT; kt++) {
        cpwait<2>();
        __syncthreads();
        float* xsf = Xs[kt & 3];
        if (bnsc) {
            int k0 = kt * 16;
#pragma unroll
            for (int i = 0; i < 8; i++) {
                int e = t + i * 128;
                int r = e >> 6, c = e & 63;
                float x = xsf[r * 72 + c];
                xsf[r * 72 + c] = fmaxf(x * bnsc[k0 + r] + bnsh[k0 + r], 0.f);
            }
            __syncthreads();
        }
        const uint32_t* ws = (const uint32_t*)Ws[kt & 3];
        const uint32_t* xs = (const uint32_t*)xsf;
#pragma unroll
        for (int s = 0; s < 2; s++) {
            uint32_t a0 = ws[(warp * 16 + l4) * 20 + 8 * s + lm4];
            uint32_t a1 = ws[(warp * 16 + l4 + 8) * 20 + 8 * s + lm4];
            uint32_t a2 = ws[(warp * 16 + l4) * 20 + 8 * s + lm4 + 4];
            uint32_t a3 = ws[(warp * 16 + l4 + 8) * 20 + 8 * s + lm4 + 4];
#pragma unroll
            for (int nt = 0; nt < 8; nt++) {
                uint32_t b0 = xs[(8 * s + lm4) * 72 + 8 * nt + l4];
                uint32_t b1 = xs[(8 * s + lm4 + 4) * 72 + 8 * nt + l4];
                mma_tf32(acc[nt][0], acc[nt][1], acc[nt][2], acc[nt][3], a0, a1, a2, a3, b0, b1);
            }
        }
        __syncthreads();
        int nk = kt + 3;
        if (nk < KT) fill(nk & 3, nk * 16);
        cpcommit();
    }

    const int rA = row0 + warp * 16 + l4;
    const int rB = rA + 8;
    const float bvA = bias[rA], bvB = bias[rB];
    if (mode == 0) {
        float* Y = (float*)Yout;
#pragma unroll
        for (int nt = 0; nt < 8; nt++) {
            int col = col0 + 8 * nt + 2 * lm4;
            *(float2*)(Y + (size_t)rA * Npts + col) = make_float2(acc[nt][0] + bvA, acc[nt][1] + bvA);
            *(float2*)(Y + (size_t)rB * Npts + col) = make_float2(acc[nt][2] + bvB, acc[nt][3] + bvB);
        }
    } else if (mode == 1) {   // K: bf16 [head][key][dim]
        __nv_bfloat16* kb = (__nv_bfloat16*)Yout;
        int hA = rA >> 5, dA = rA & 31, hB = rB >> 5, dB = rB & 31;
#pragma unroll
        for (int nt = 0; nt < 8; nt++) {
            int col = col0 + 8 * nt + 2 * lm4;
            kb[hA * (NPT * HD) + col * HD + dA]       = __float2bfloat16(acc[nt][0] + bvA);
            kb[hA * (NPT * HD) + (col + 1) * HD + dA] = __float2bfloat16(acc[nt][1] + bvA);
            kb[hB * (NPT * HD) + col * HD + dB]       = __float2bfloat16(acc[nt][2] + bvB);
            kb[hB * (NPT * HD) + (col + 1) * HD + dB] = __float2bfloat16(acc[nt][3] + bvB);
        }
    } else {                  // V: bf16 [dim-row][key]
        __nv_bfloat16* vb = (__nv_bfloat16*)Yout;
#pragma unroll
        for (int nt = 0; nt < 8; nt++) {
            int col = col0 + 8 * nt + 2 * lm4;
            *(uint32_t*)(vb + (size_t)rA * Npts + col) = packbf(acc[nt][0] + bvA, acc[nt][1] + bvA);
            *(uint32_t*)(vb + (size_t)rB * Npts + col) = packbf(acc[nt][2] + bvB, acc[nt][3] + bvB);
        }
    }
}

// ==================== bf16 MMA flash attention, split-K, max-free, ldmatrix ====================
#define KSROW 80
#define VSROW 272
#define KSBYTES (128 * KSROW)
#define VSBYTES (32 * VSROW)
#define BUFBYTES (KSBYTES + VSBYTES)
#define ATTN_SMEM (2 * BUFBYTES)           // 37888

__global__ __launch_bounds__(128) void attn_pass1_kernel(const float* __restrict__ q,
                                                         const __nv_bfloat16* __restrict__ ktb,
                                                         const __nv_bfloat16* __restrict__ vb,
                                                         float* __restrict__ po,
                                                         float* __restrict__ pl) {
    extern __shared__ char smc[];
    const int head = blockIdx.y;
    const int split = blockIdx.z;
    const int n0 = blockIdx.x * 64;
    const int t = threadIdx.x;
    const int warp = t >> 5, lane = t & 31;
    const int l4 = lane >> 2, lm4 = lane & 3;
    const int lr = lane & 7, lg = lane >> 3;
    const int qg0 = n0 + warp * 16 + l4;
    const int key0 = split * KEYS_PER_SPLIT;

    const float* qh = q + head * HD * NPT;
    const __nv_bfloat16* kth = ktb + head * (NPT * HD);
    const __nv_bfloat16* vh = vb + head * (HD * NPT);

    const float qscale = 0.17677669529663687f * 1.4426950408889634f;
    uint32_t aQ[2][4];
#pragma unroll
    for (int s = 0; s < 2; s++) {
        int d0 = 16 * s + 2 * lm4;
        aQ[s][0] = packbf(qh[d0 * NPT + qg0] * qscale,       qh[(d0 + 1) * NPT + qg0] * qscale);
        aQ[s][1] = packbf(qh[d0 * NPT + qg0 + 8] * qscale,   qh[(d0 + 1) * NPT + qg0 + 8] * qscale);
        aQ[s][2] = packbf(qh[(d0 + 8) * NPT + qg0] * qscale, qh[(d0 + 9) * NPT + qg0] * qscale);
        aQ[s][3] = packbf(qh[(d0 + 8) * NPT + qg0 + 8] * qscale, qh[(d0 + 9) * NPT + qg0 + 8] * qscale);
    }

    float oAcc[4][4];
#pragma unroll
    for (int i = 0; i < 4; i++)
#pragma unroll
        for (int j = 0; j < 4; j++) oAcc[i][j] = 0.f;
    float l0 = 0.f, l1 = 0.f;

    uint32_t sm0 = (uint32_t)__cvta_generic_to_shared(smc);

    auto fill = [&](int buf, int m0g) {
        uint32_t ksb = sm0 + buf * BUFBYTES;
        uint32_t vsb = ksb + KSBYTES;
#pragma unroll
        for (int i = 0; i < 4; i++) {
            int idx = t + i * 128;
            int key = idx >> 2, c = idx & 3;
            cpasync16(ksb + key * KSROW + c * 16, kth + (m0g + key) * HD + c * 8);
        }
#pragma unroll
        for (int i = 0; i < 4; i++) {
            int idx = t + i * 128;
            int d = idx >> 4, c = idx & 15;
            cpasync16(vsb + d * VSROW + c * 16, vh + d * NPT + m0g + c * 8);
        }
    };

    const int NTILES = KEYS_PER_SPLIT / 128;   // 8
    fill(0, key0);
    cpcommit();

    for (int it = 0; it < NTILES; it++) {
        if (it + 1 < NTILES) { fill((it + 1) & 1, key0 + (it + 1) * 128); cpcommit(); cpwait<1>(); }
        else cpwait<0>();
        __syncthreads();

        const uint32_t ksaddr = sm0 + (it & 1) * BUFBYTES;
        const uint32_t vsaddr = ksaddr + KSBYTES;
        const uint32_t ks_lane = ksaddr + lr * KSROW + lg * 16;
        const uint32_t vs_lane = vsaddr + lr * VSROW + lg * 16;

        uint32_t aP[8][4];
#pragma unroll
        for (int kp = 0; kp < 8; kp++) {
            float p[2][4];
#pragma unroll
            for (int h = 0; h < 2; h++) {
                int nt = 2 * kp + h;
                uint32_t b00, b01, b10, b11;
                ldsm4(b00, b01, b10, b11, ks_lane + nt * (8 * KSROW));
                float c0 = 0.f, c1 = 0.f, c2 = 0.f, c3 = 0.f;
                mma_bf16(c0, c1, c2, c3, aQ[0][0], aQ[0][1], aQ[0][2], aQ[0][3], b00, b01);
                mma_bf16(c0, c1, c2, c3, aQ[1][0], aQ[1][1], aQ[1][2], aQ[1][3], b10, b11);
                p[h][0] = ex2f(c0); p[h][1] = ex2f(c1);
                p[h][2] = ex2f(c2); p[h][3] = ex2f(c3);
                l0 += p[h][0] + p[h][1];
                l1 += p[h][2] + p[h][3];
            }
            aP[kp][0] = packbf(p[0][0], p[0][1]);
            aP[kp][1] = packbf(p[0][2], p[0][3]);
            aP[kp][2] = packbf(p[1][0], p[1][1]);
            aP[kp][3] = packbf(p[1][2], p[1][3]);
        }

#pragma unroll
        for (int ntd = 0; ntd < 4; ntd++) {
            float c0 = oAcc[ntd][0], c1 = oAcc[ntd][1], c2 = oAcc[ntd][2], c3 = oAcc[ntd][3];
            uint32_t vrow = vs_lane + ntd * (8 * VSROW);
#pragma unroll
            for (int kp2 = 0; kp2 < 4; kp2++) {
                uint32_t m0, m1, m2, m3;
                ldsm4(m0, m1, m2, m3, vrow + kp2 * 64);
                mma_bf16(c0, c1, c2, c3, aP[2 * kp2][0], aP[2 * kp2][1], aP[2 * kp2][2], aP[2 * kp2][3], m0, m1);
                mma_bf16(c0, c1, c2, c3, aP[2 * kp2 + 1][0], aP[2 * kp2 + 1][1], aP[2 * kp2 + 1][2], aP[2 * kp2 + 1][3], m2, m3);
            }
            oAcc[ntd][0] = c0; oAcc[ntd][1] = c1; oAcc[ntd][2] = c2; oAcc[ntd][3] = c3;
        }
        __syncthreads();
    }

    l0 += __shfl_xor_sync(0xffffffffu, l0, 1);
    l0 += __shfl_xor_sync(0xffffffffu, l0, 2);
    l1 += __shfl_xor_sync(0xffffffffu, l1, 1);
    l1 += __shfl_xor_sync(0xffffffffu, l1, 2);

    float* pp = po + (size_t)(split * NH + head) * HD * NPT;
#pragma unroll
    for (int ntd = 0; ntd < 4; ntd++) {
        int dim = 8 * ntd + 2 * lm4;
        pp[dim * NPT + qg0]           = oAcc[ntd][0];
        pp[(dim + 1) * NPT + qg0]     = oAcc[ntd][1];
        pp[dim * NPT + qg0 + 8]       = oAcc[ntd][2];
        pp[(dim + 1) * NPT + qg0 + 8] = oAcc[ntd][3];
    }
    if (lm4 == 0) {
        int base = (split * NH + head) * NPT;
        pl[base + qg0] = l0;
        pl[base + qg0 + 8] = l1;
    }
}

__global__ __launch_bounds__(128) void attn_combine_kernel(const float* __restrict__ po,
                                                           const float* __restrict__ pl,
                                                           float* __restrict__ out) {
    const int n = blockIdx.x * 128 + threadIdx.x;
    const int head = blockIdx.y;
    const int d0 = blockIdx.z * 8;

    float L = 0.f;
#pragma unroll
    for (int s = 0; s < KSPLIT; s++)
        L += pl[(s * NH + head) * NPT + n];
    float inv = 1.f / L;
#pragma unroll
    for (int d = 0; d < 8; d++) {
        float acc = 0.f;
#pragma unroll
        for (int s = 0; s < KSPLIT; s++)
            acc += po[((size_t)(s * NH + head) * HD + d0 + d) * NPT + n];
        out[(head * HD + d0 + d) * NPT + n] = acc * inv;
    }
}

// -------------------- BN stats (proven standalone) --------------------
__global__ void bn_stats_kernel(const float* __restrict__ h,
                                const float* __restrict__ gamma,
                                const float* __restrict__ beta,
                                float* __restrict__ scale,
                                float* __restrict__ shift, int Npts) {
    int c = blockIdx.x;
    int t = threadIdx.x;
    float s = 0.f, ss = 0.f;
    for (int n = t; n < Npts; n += blockDim.x) {
        float x = h[c * Npts + n];
        s += x; ss += x * x;
    }
    __shared__ float rs[256], rss[256];
    rs[t] = s; rss[t] = ss;
    __syncthreads();
    for (int o = 128; o > 0; o >>= 1) {
        if (t < o) { rs[t] += rs[t + o]; rss[t] += rss[t + o]; }
        __syncthreads();
    }
    if (t == 0) {
        float mean = rs[0] / (float)Npts;
        float var = rss[0] / (float)Npts - mean * mean;
        float sc = gamma[c] * rsqrtf(var + EPSBN);
        scale[c] = sc;
        shift[c] = beta[c] - mean * sc;
    }
}

// -------------------- tail --------------------
__global__ void final_kernel(const float* __restrict__ eigen,
                             const float* __restrict__ h2,
                             const float* __restrict__ wt,
                             const float* __restrict__ bt,
                             float* __restrict__ out, int Npts) {
    int n = blockIdx.x * blockDim.x + threadIdx.x;
    if (n >= Npts) return;
    float a0 = bt[0], a1 = bt[1], a2 = bt[2];
#pragma unroll 4
    for (int c = 0; c < CCH; c++) {
        float x = eigen[c * Npts + n] + h2[c * Npts + n];
        a0 += wt[c] * x;
        a1 += wt[CCH + c] * x;
        a2 += wt[2 * CCH + c] * x;
    }
    out[n * 3 + 0] = a0;
    out[n * 3 + 1] = a1;
    out[n * 3 + 2] = a2;
}

// -------------------- launch --------------------
extern "C" void kernel_launch(void* const* d_in, const int* in_sizes, int n_in,
                              void* d_out, int out_size) {
    const float* eigen = (const float*)d_in[0];
    const float* wq  = (const float*)d_in[1];
    const float* bq  = (const float*)d_in[2];
    const float* wk  = (const float*)d_in[3];
    const float* bk  = (const float*)d_in[4];
    const float* wv  = (const float*)d_in[5];
    const float* bv  = (const float*)d_in[6];
    const float* wmh = (const float*)d_in[7];
    const float* bmh = (const float*)d_in[8];
    const float* wc1 = (const float*)d_in[9];
    const float* bc1 = (const float*)d_in[10];
    const float* gamma = (const float*)d_in[11];
    const float* beta  = (const float*)d_in[12];
    const float* wc2 = (const float*)d_in[13];
    const float* bc2 = (const float*)d_in[14];
    const float* wt  = (const float*)d_in[15];
    const float* bt  = (const float*)d_in[16];
    float* out = (float*)d_out;

    float *gq, *gpo, *gpl, *gattn, *gmh, *gh1, *gh2, *gbnsc, *gbnsh;
    __nv_bfloat16 *gktb, *gvb;
    cudaGetSymbolAddress((void**)&gq, g_q);
    cudaGetSymbolAddress((void**)&gktb, g_ktb_raw);
    cudaGetSymbolAddress((void**)&gvb, g_vb_raw);
    cudaGetSymbolAddress((void**)&gpo, g_po);
    cudaGetSymbolAddress((void**)&gpl, g_pl);
    cudaGetSymbolAddress((void**)&gattn, g_attn);
    cudaGetSymbolAddress((void**)&gmh, g_mh);
    cudaGetSymbolAddress((void**)&gh1, g_h1);
    cudaGetSymbolAddress((void**)&gh2, g_h2);
    cudaGetSymbolAddress((void**)&gbnsc, g_bnscale);
    cudaGetSymbolAddress((void**)&gbnsh, g_bnshift);

    const int N = NPT;

    // 1) fused QKV projections
    conv_mma_kernel<<<dim3(N / 64, 6), 128>>>(wq, eigen, eigen, CCH, bq, gq, CCH, N, 0,
                                              nullptr, nullptr,
                                              wk, bk, gktb, wv, bv, gvb, 1);

    // 2) attention: split-K pass 1 + combine
    attn_pass1_kernel<<<dim3(N / 64, NH, KSPLIT), 128, ATTN_SMEM>>>(gq, gktb, gvb, gpo, gpl);
    attn_combine_kernel<<<dim3(N / 128, NH, HD / 8), 128>>>(gpo, gpl, gattn);

    // 3) mh projection
    conv_mma_kernel<<<dim3(N / 64, CCH / 64), 128>>>(wmh, gattn, gattn, CCH, bmh, gmh, CCH, N, 0,
                                                     nullptr, nullptr,
                                                     nullptr, nullptr, nullptr,
                                                     nullptr, nullptr, nullptr, 0);

    // 4) cat_filter conv1
    conv_mma_kernel<<<dim3(N / 64, 2 * CCH / 64), 128>>>(wc1, eigen, gmh, CCH, bc1, gh1, 2 * CCH, N, 0,
                                                         nullptr, nullptr,
                                                         nullptr, nullptr, nullptr,
                                                         nullptr, nullptr, nullptr, 0);

    // 5) BN stats (standalone, proven)
    bn_stats_kernel<<<2 * CCH, 256>>>(gh1, gamma, beta, gbnsc, gbnsh, N);

    // 6) conv2 with fused BN apply + relu on X tiles (replaces bn_apply pass)
    conv_mma_kernel<<<dim3(N / 64, CCH / 64), 128>>>(wc2, gh1, gh1, 2 * CCH, bc2, gh2, 2 * CCH, N, 0,
                                                     gbnsc, gbnsh,
                                                     nullptr, nullptr, nullptr,
                                                     nullptr, nullptr, nullptr, 0);

    // 7) residual + tran_layer
    final_kernel<<<(N + 127) / 128, 128>>>(eigen, gh2, wt, bt, out, N);
}

// round 17
// speedup vs baseline: 1.0420x; 1.0420x over previous
#include <cuda_runtime.h>
#include <cuda_bf16.h>
#include <math_constants.h>
#include <stdint.h>

#define CCH   128
#define NH    4
#define HD    32
#define NPT   4096
#define EPSBN 1e-5f
#define KSPLIT 4
#define KEYS_PER_SPLIT (NPT / KSPLIT)   // 1024

// -------------------- scratch --------------------
__device__ float g_q[CCH * NPT];
__device__ float4 g_ktb_raw[NH * NPT * HD / 8];          // bf16 [head][key][dim]
__device__ float4 g_vb_raw[NH * HD * NPT / 8];           // bf16 [head][dim][key]
__device__ float g_po[KSPLIT * NH * HD * NPT];
__device__ float g_pl[KSPLIT * NH * NPT];
__device__ float g_attn[CCH * NPT];
__device__ float g_mh[CCH * NPT];
__device__ float g_h1[2 * CCH * NPT];
__device__ float g_h2[CCH * NPT];
__device__ float g_bnscale[2 * CCH];
__device__ float g_bnshift[2 * CCH];

// -------------------- ptx helpers --------------------
__device__ __forceinline__ float ex2f(float x) {
    float r; asm("ex2.approx.ftz.f32 %0, %1;" : "=f"(r) : "f"(x)); return r;
}
__device__ __forceinline__ uint32_t packbf(float lo, float hi) {
    uint32_t r; asm("cvt.rn.bf16x2.f32 %0, %1, %2;" : "=r"(r) : "f"(hi), "f"(lo)); return r;
}
__device__ __forceinline__ void mma_tf32(float& c0, float& c1, float& c2, float& c3,
                                         uint32_t a0, uint32_t a1, uint32_t a2, uint32_t a3,
                                         uint32_t b0, uint32_t b1) {
    asm volatile("mma.sync.aligned.m16n8k8.row.col.f32.tf32.tf32.f32 "
                 "{%0,%1,%2,%3}, {%4,%5,%6,%7}, {%8,%9}, {%0,%1,%2,%3};"
                 : "+f"(c0), "+f"(c1), "+f"(c2), "+f"(c3)
                 : "r"(a0), "r"(a1), "r"(a2), "r"(a3), "r"(b0), "r"(b1));
}
__device__ __forceinline__ void mma_bf16(float& c0, float& c1, float& c2, float& c3,
                                         uint32_t a0, uint32_t a1, uint32_t a2, uint32_t a3,
                                         uint32_t b0, uint32_t b1) {
    asm volatile("mma.sync.aligned.m16n8k16.row.col.f32.bf16.bf16.f32 "
                 "{%0,%1,%2,%3}, {%4,%5,%6,%7}, {%8,%9}, {%0,%1,%2,%3};"
                 : "+f"(c0), "+f"(c1), "+f"(c2), "+f"(c3)
                 : "r"(a0), "r"(a1), "r"(a2), "r"(a3), "r"(b0), "r"(b1));
}
__device__ __forceinline__ void ldsm4(uint32_t& r0, uint32_t& r1, uint32_t& r2, uint32_t& r3,
                                      uint32_t addr) {
    asm volatile("ldmatrix.sync.aligned.m8n8.x4.shared.b16 {%0,%1,%2,%3}, [%4];"
                 : "=r"(r0), "=r"(r1), "=r"(r2), "=r"(r3) : "r"(addr));
}
__device__ __forceinline__ void cpasync16(uint32_t dst, const void* src) {
    asm volatile("cp.async.cg.shared.global [%0], [%1], 16;" :: "r"(dst), "l"(src));
}
__device__ __forceinline__ void cpcommit() { asm volatile("cp.async.commit_group;"); }
template <int N> __device__ __forceinline__ void cpwait() {
    asm volatile("cp.async.wait_group %0;" :: "n"(N));
}

// ==================== tf32 MMA conv1x1, 4-stage pipelined (R13/R14-proven) ====================
#define CSTAGES 4

__global__ __launch_bounds__(128) void conv_mma_kernel(
    const float* __restrict__ W, const float* __restrict__ X,
    const float* __restrict__ X2, int CinX,
    const float* __restrict__ bias, void* __restrict__ Yout,
    int Cin, int Npts, int mode,
    const float* W1, const float* b1, void* Y1,
    const float* W2, const float* b2, void* Y2, int fused) {
    __shared__ __align__(16) float Ws[CSTAGES][64 * 20];
    __shared__ __align__(16) float Xs[CSTAGES][16 * 72];

    const int t = threadIdx.x;
    const int warp = t >> 5, lane = t & 31;
    const int l4 = lane >> 2, lm4 = lane & 3;
    int row0, by = blockIdx.y;
    if (fused) {
        int grp = by >> 1;
        row0 = (by & 1) * 64;
        if (grp == 1) { W = W1; bias = b1; Yout = Y1; mode = 1; }
        else if (grp == 2) { W = W2; bias = b2; Yout = Y2; mode = 2; }
    } else {
        row0 = by * 64;
    }
    const int col0 = blockIdx.x * 64;

    float acc[8][4];
#pragma unroll
    for (int i = 0; i < 8; i++)
#pragma unroll
        for (int j = 0; j < 4; j++) acc[i][j] = 0.f;

    uint32_t wb[CSTAGES], xb[CSTAGES];
#pragma unroll
    for (int s = 0; s < CSTAGES; s++) {
        wb[s] = (uint32_t)__cvta_generic_to_shared(Ws[s]);
        xb[s] = (uint32_t)__cvta_generic_to_shared(Xs[s]);
    }

    auto fill = [&](int buf, int k0) {
#pragma unroll
        for (int i = 0; i < 2; i++) {
            int idx = t + i * 128;
            int r = idx >> 2, c = idx & 3;
            cpasync16(wb[buf] + (r * 20 + c * 4) * 4, W + (size_t)(row0 + r) * Cin + k0 + c * 4);
        }
#pragma unroll
        for (int i = 0; i < 2; i++) {
            int idx = t + i * 128;
            int r = idx >> 4, c = idx & 15;
            int kr = k0 + r;
            const float* base = (kr < CinX) ? (X + (size_t)kr * Npts)
                                            : (X2 + (size_t)(kr - CinX) * Npts);
            cpasync16(xb[buf] + (r * 72 + c * 4) * 4, base + col0 + c * 4);
        }
    };

    const int KT = Cin >> 4;
#pragma unroll
    for (int p = 0; p < 3; p++) {
        fill(p, p * 16);
        cpcommit();
    }
    for (int kt = 0; kt < KT; kt++) {
        cpwait<2>();
        __syncthreads();
        const uint32_t* ws = (const uint32_t*)Ws[kt & 3];
        const uint32_t* xs = (const uint32_t*)Xs[kt & 3];
#pragma unroll
        for (int s = 0; s < 2; s++) {
            uint32_t a0 = ws[(warp * 16 + l4) * 20 + 8 * s + lm4];
            uint32_t a1 = ws[(warp * 16 + l4 + 8) * 20 + 8 * s + lm4];
            uint32_t a2 = ws[(warp * 16 + l4) * 20 + 8 * s + lm4 + 4];
            uint32_t a3 = ws[(warp * 16 + l4 + 8) * 20 + 8 * s + lm4 + 4];
#pragma unroll
            for (int nt = 0; nt < 8; nt++) {
                uint32_t b0 = xs[(8 * s + lm4) * 72 + 8 * nt + l4];
                uint32_t b1 = xs[(8 * s + lm4 + 4) * 72 + 8 * nt + l4];
                mma_tf32(acc[nt][0], acc[nt][1], acc[nt][2], acc[nt][3], a0, a1, a2, a3, b0, b1);
            }
        }
        __syncthreads();
        int nk = kt + 3;
        if (nk < KT) fill(nk & 3, nk * 16);
        cpcommit();
    }

    const int rA = row0 + warp * 16 + l4;
    const int rB = rA + 8;
    const float bvA = bias[rA], bvB = bias[rB];
    if (mode == 0) {
        float* Y = (float*)Yout;
#pragma unroll
        for (int nt = 0; nt < 8; nt++) {
            int col = col0 + 8 * nt + 2 * lm4;
            *(float2*)(Y + (size_t)rA * Npts + col) = make_float2(acc[nt][0] + bvA, acc[nt][1] + bvA);
            *(float2*)(Y + (size_t)rB * Npts + col) = make_float2(acc[nt][2] + bvB, acc[nt][3] + bvB);
        }
    } else if (mode == 1) {   // K: bf16 [head][key][dim]
        __nv_bfloat16* kb = (__nv_bfloat16*)Yout;
        int hA = rA >> 5, dA = rA & 31, hB = rB >> 5, dB = rB & 31;
#pragma unroll
        for (int nt = 0; nt < 8; nt++) {
            int col = col0 + 8 * nt + 2 * lm4;
            kb[hA * (NPT * HD) + col * HD + dA]       = __float2bfloat16(acc[nt][0] + bvA);
            kb[hA * (NPT * HD) + (col + 1) * HD + dA] = __float2bfloat16(acc[nt][1] + bvA);
            kb[hB * (NPT * HD) + col * HD + dB]       = __float2bfloat16(acc[nt][2] + bvB);
            kb[hB * (NPT * HD) + (col + 1) * HD + dB] = __float2bfloat16(acc[nt][3] + bvB);
        }
    } else {                  // V: bf16 [dim-row][key]
        __nv_bfloat16* vb = (__nv_bfloat16*)Yout;
#pragma unroll
        for (int nt = 0; nt < 8; nt++) {
            int col = col0 + 8 * nt + 2 * lm4;
            *(uint32_t*)(vb + (size_t)rA * Npts + col) = packbf(acc[nt][0] + bvA, acc[nt][1] + bvA);
            *(uint32_t*)(vb + (size_t)rB * Npts + col) = packbf(acc[nt][2] + bvB, acc[nt][3] + bvB);
        }
    }
}

// ==================== bf16 MMA flash attention, split-K, max-free, ldmatrix ====================
#define KSROW 80
#define VSROW 272
#define KSBYTES (128 * KSROW)
#define VSBYTES (32 * VSROW)
#define BUFBYTES (KSBYTES + VSBYTES)
#define ATTN_SMEM (2 * BUFBYTES)           // 37888

__global__ __launch_bounds__(128) void attn_pass1_kernel(const float* __restrict__ q,
                                                         const __nv_bfloat16* __restrict__ ktb,
                                                         const __nv_bfloat16* __restrict__ vb,
                                                         float* __restrict__ po,
                                                         float* __restrict__ pl) {
    extern __shared__ char smc[];
    const int head = blockIdx.y;
    const int split = blockIdx.z;
    const int n0 = blockIdx.x * 64;
    const int t = threadIdx.x;
    const int warp = t >> 5, lane = t & 31;
    const int l4 = lane >> 2, lm4 = lane & 3;
    const int lr = lane & 7, lg = lane >> 3;
    const int qg0 = n0 + warp * 16 + l4;
    const int key0 = split * KEYS_PER_SPLIT;

    const float* qh = q + head * HD * NPT;
    const __nv_bfloat16* kth = ktb + head * (NPT * HD);
    const __nv_bfloat16* vh = vb + head * (HD * NPT);

    const float qscale = 0.17677669529663687f * 1.4426950408889634f;
    uint32_t aQ[2][4];
#pragma unroll
    for (int s = 0; s < 2; s++) {
        int d0 = 16 * s + 2 * lm4;
        aQ[s][0] = packbf(qh[d0 * NPT + qg0] * qscale,       qh[(d0 + 1) * NPT + qg0] * qscale);
        aQ[s][1] = packbf(qh[d0 * NPT + qg0 + 8] * qscale,   qh[(d0 + 1) * NPT + qg0 + 8] * qscale);
        aQ[s][2] = packbf(qh[(d0 + 8) * NPT + qg0] * qscale, qh[(d0 + 9) * NPT + qg0] * qscale);
        aQ[s][3] = packbf(qh[(d0 + 8) * NPT + qg0 + 8] * qscale, qh[(d0 + 9) * NPT + qg0 + 8] * qscale);
    }

    float oAcc[4][4];
#pragma unroll
    for (int i = 0; i < 4; i++)
#pragma unroll
        for (int j = 0; j < 4; j++) oAcc[i][j] = 0.f;
    float l0 = 0.f, l1 = 0.f;

    uint32_t sm0 = (uint32_t)__cvta_generic_to_shared(smc);

    auto fill = [&](int buf, int m0g) {
        uint32_t ksb = sm0 + buf * BUFBYTES;
        uint32_t vsb = ksb + KSBYTES;
#pragma unroll
        for (int i = 0; i < 4; i++) {
            int idx = t + i * 128;
            int key = idx >> 2, c = idx & 3;
            cpasync16(ksb + key * KSROW + c * 16, kth + (m0g + key) * HD + c * 8);
        }
#pragma unroll
        for (int i = 0; i < 4; i++) {
            int idx = t + i * 128;
            int d = idx >> 4, c = idx & 15;
            cpasync16(vsb + d * VSROW + c * 16, vh + d * NPT + m0g + c * 8);
        }
    };

    const int NTILES = KEYS_PER_SPLIT / 128;   // 8
    fill(0, key0);
    cpcommit();

    for (int it = 0; it < NTILES; it++) {
        if (it + 1 < NTILES) { fill((it + 1) & 1, key0 + (it + 1) * 128); cpcommit(); cpwait<1>(); }
        else cpwait<0>();
        __syncthreads();

        const uint32_t ksaddr = sm0 + (it & 1) * BUFBYTES;
        const uint32_t vsaddr = ksaddr + KSBYTES;
        const uint32_t ks_lane = ksaddr + lr * KSROW + lg * 16;
        const uint32_t vs_lane = vsaddr + lr * VSROW + lg * 16;

        uint32_t aP[8][4];
#pragma unroll
        for (int kp = 0; kp < 8; kp++) {
            float p[2][4];
#pragma unroll
            for (int h = 0; h < 2; h++) {
                int nt = 2 * kp + h;
                uint32_t b00, b01, b10, b11;
                ldsm4(b00, b01, b10, b11, ks_lane + nt * (8 * KSROW));
                float c0 = 0.f, c1 = 0.f, c2 = 0.f, c3 = 0.f;
                mma_bf16(c0, c1, c2, c3, aQ[0][0], aQ[0][1], aQ[0][2], aQ[0][3], b00, b01);
                mma_bf16(c0, c1, c2, c3, aQ[1][0], aQ[1][1], aQ[1][2], aQ[1][3], b10, b11);
                p[h][0] = ex2f(c0); p[h][1] = ex2f(c1);
                p[h][2] = ex2f(c2); p[h][3] = ex2f(c3);
                l0 += p[h][0] + p[h][1];
                l1 += p[h][2] + p[h][3];
            }
            aP[kp][0] = packbf(p[0][0], p[0][1]);
            aP[kp][1] = packbf(p[0][2], p[0][3]);
            aP[kp][2] = packbf(p[1][0], p[1][1]);
            aP[kp][3] = packbf(p[1][2], p[1][3]);
        }

#pragma unroll
        for (int ntd = 0; ntd < 4; ntd++) {
            float c0 = oAcc[ntd][0], c1 = oAcc[ntd][1], c2 = oAcc[ntd][2], c3 = oAcc[ntd][3];
            uint32_t vrow = vs_lane + ntd * (8 * VSROW);
#pragma unroll
            for (int kp2 = 0; kp2 < 4; kp2++) {
                uint32_t m0, m1, m2, m3;
                ldsm4(m0, m1, m2, m3, vrow + kp2 * 64);
                mma_bf16(c0, c1, c2, c3, aP[2 * kp2][0], aP[2 * kp2][1], aP[2 * kp2][2], aP[2 * kp2][3], m0, m1);
                mma_bf16(c0, c1, c2, c3, aP[2 * kp2 + 1][0], aP[2 * kp2 + 1][1], aP[2 * kp2 + 1][2], aP[2 * kp2 + 1][3], m2, m3);
            }
            oAcc[ntd][0] = c0; oAcc[ntd][1] = c1; oAcc[ntd][2] = c2; oAcc[ntd][3] = c3;
        }
        __syncthreads();
    }

    l0 += __shfl_xor_sync(0xffffffffu, l0, 1);
    l0 += __shfl_xor_sync(0xffffffffu, l0, 2);
    l1 += __shfl_xor_sync(0xffffffffu, l1, 1);
    l1 += __shfl_xor_sync(0xffffffffu, l1, 2);

    float* pp = po + (size_t)(split * NH + head) * HD * NPT;
#pragma unroll
    for (int ntd = 0; ntd < 4; ntd++) {
        int dim = 8 * ntd + 2 * lm4;
        pp[dim * NPT + qg0]           = oAcc[ntd][0];
        pp[(dim + 1) * NPT + qg0]     = oAcc[ntd][1];
        pp[dim * NPT + qg0 + 8]       = oAcc[ntd][2];
        pp[(dim + 1) * NPT + qg0 + 8] = oAcc[ntd][3];
    }
    if (lm4 == 0) {
        int base = (split * NH + head) * NPT;
        pl[base + qg0] = l0;
        pl[base + qg0 + 8] = l1;
    }
}

__global__ __launch_bounds__(128) void attn_combine_kernel(const float* __restrict__ po,
                                                           const float* __restrict__ pl,
                                                           float* __restrict__ out) {
    const int n = blockIdx.x * 128 + threadIdx.x;
    const int head = blockIdx.y;
    const int d0 = blockIdx.z * 8;

    float L = 0.f;
#pragma unroll
    for (int s = 0; s < KSPLIT; s++)
        L += pl[(s * NH + head) * NPT + n];
    float inv = 1.f / L;
#pragma unroll
    for (int d = 0; d < 8; d++) {
        float acc = 0.f;
#pragma unroll
        for (int s = 0; s < KSPLIT; s++)
            acc += po[((size_t)(s * NH + head) * HD + d0 + d) * NPT + n];
        out[(head * HD + d0 + d) * NPT + n] = acc * inv;
    }
}

// -------------------- misc small kernels --------------------
__global__ void bn_stats_kernel(const float* __restrict__ h,
                                const float* __restrict__ gamma,
                                const float* __restrict__ beta,
                                float* __restrict__ scale,
                                float* __restrict__ shift, int Npts) {
    int c = blockIdx.x;
    int t = threadIdx.x;
    float s = 0.f, ss = 0.f;
    for (int n = t; n < Npts; n += blockDim.x) {
        float x = h[c * Npts + n];
        s += x; ss += x * x;
    }
    __shared__ float rs[256], rss[256];
    rs[t] = s; rss[t] = ss;
    __syncthreads();
    for (int o = 128; o > 0; o >>= 1) {
        if (t < o) { rs[t] += rs[t + o]; rss[t] += rss[t + o]; }
        __syncthreads();
    }
    if (t == 0) {
        float mean = rs[0] / (float)Npts;
        float var = rss[0] / (float)Npts - mean * mean;
        float sc = gamma[c] * rsqrtf(var + EPSBN);
        scale[c] = sc;
        shift[c] = beta[c] - mean * sc;
    }
}

__global__ void bn_apply_relu_kernel(float* __restrict__ h,
                                     const float* __restrict__ scale,
                                     const float* __restrict__ shift,
                                     int Npts, int total) {
    int i = blockIdx.x * blockDim.x + threadIdx.x;
    if (i < total) {
        int c = i / Npts;
        float x = h[i] * scale[c] + shift[c];
        h[i] = fmaxf(x, 0.f);
    }
}

__global__ void final_kernel(const float* __restrict__ eigen,
                             const float* __restrict__ h2,
                             const float* __restrict__ wt,
                             const float* __restrict__ bt,
                             float* __restrict__ out, int Npts) {
    int n = blockIdx.x * blockDim.x + threadIdx.x;
    if (n >= Npts) return;
    float a0 = bt[0], a1 = bt[1], a2 = bt[2];
#pragma unroll 4
    for (int c = 0; c < CCH; c++) {
        float x = eigen[c * Npts + n] + h2[c * Npts + n];
        a0 += wt[c] * x;
        a1 += wt[CCH + c] * x;
        a2 += wt[2 * CCH + c] * x;
    }
    out[n * 3 + 0] = a0;
    out[n * 3 + 1] = a1;
    out[n * 3 + 2] = a2;
}

// -------------------- launch --------------------
extern "C" void kernel_launch(void* const* d_in, const int* in_sizes, int n_in,
                              void* d_out, int out_size) {
    const float* eigen = (const float*)d_in[0];
    const float* wq  = (const float*)d_in[1];
    const float* bq  = (const float*)d_in[2];
    const float* wk  = (const float*)d_in[3];
    const float* bk  = (const float*)d_in[4];
    const float* wv  = (const float*)d_in[5];
    const float* bv  = (const float*)d_in[6];
    const float* wmh = (const float*)d_in[7];
    const float* bmh = (const float*)d_in[8];
    const float* wc1 = (const float*)d_in[9];
    const float* bc1 = (const float*)d_in[10];
    const float* gamma = (const float*)d_in[11];
    const float* beta  = (const float*)d_in[12];
    const float* wc2 = (const float*)d_in[13];
    const float* bc2 = (const float*)d_in[14];
    const float* wt  = (const float*)d_in[15];
    const float* bt  = (const float*)d_in[16];
    float* out = (float*)d_out;

    float *gq, *gpo, *gpl, *gattn, *gmh, *gh1, *gh2, *gbnsc, *gbnsh;
    __nv_bfloat16 *gktb, *gvb;
    cudaGetSymbolAddress((void**)&gq, g_q);
    cudaGetSymbolAddress((void**)&gktb, g_ktb_raw);
    cudaGetSymbolAddress((void**)&gvb, g_vb_raw);
    cudaGetSymbolAddress((void**)&gpo, g_po);
    cudaGetSymbolAddress((void**)&gpl, g_pl);
    cudaGetSymbolAddress((void**)&gattn, g_attn);
    cudaGetSymbolAddress((void**)&gmh, g_mh);
    cudaGetSymbolAddress((void**)&gh1, g_h1);
    cudaGetSymbolAddress((void**)&gh2, g_h2);
    cudaGetSymbolAddress((void**)&gbnsc, g_bnscale);
    cudaGetSymbolAddress((void**)&gbnsh, g_bnshift);

    // Raise L1/shared carveout for the attention kernel: default carveout (~100KB)
    // caps residency at ~2-3 CTAs x 37.9KB; full carveout allows 6 CTAs/SM.
    // Host-side, idempotent, capture-safe.
    cudaFuncSetAttribute(attn_pass1_kernel,
                         cudaFuncAttributePreferredSharedMemoryCarveout, 100);

    const int N = NPT;

    // 1) fused QKV projections
    conv_mma_kernel<<<dim3(N / 64, 6), 128>>>(wq, eigen, eigen, CCH, bq, gq, CCH, N, 0,
                                              wk, bk, gktb, wv, bv, gvb, 1);

    // 2) attention: split-K pass 1 + combine
    attn_pass1_kernel<<<dim3(N / 64, NH, KSPLIT), 128, ATTN_SMEM>>>(gq, gktb, gvb, gpo, gpl);
    attn_combine_kernel<<<dim3(N / 128, NH, HD / 8), 128>>>(gpo, gpl, gattn);

    // 3) mh projection
    conv_mma_kernel<<<dim3(N / 64, CCH / 64), 128>>>(wmh, gattn, gattn, CCH, bmh, gmh, CCH, N, 0,
                                                     nullptr, nullptr, nullptr,
                                                     nullptr, nullptr, nullptr, 0);

    // 4) cat_filter conv1
    conv_mma_kernel<<<dim3(N / 64, 2 * CCH / 64), 128>>>(wc1, eigen, gmh, CCH, bc1, gh1, 2 * CCH, N, 0,
                                                         nullptr, nullptr, nullptr,
                                                         nullptr, nullptr, nullptr, 0);

    // 5) batchnorm + relu
    bn_stats_kernel<<<2 * CCH, 256>>>(gh1, gamma, beta, gbnsc, gbnsh, N);
    bn_apply_relu_kernel<<<(2 * CCH * N + 255) / 256, 256>>>(gh1, gbnsc, gbnsh, N, 2 * CCH * N);

    // 6) cat_filter conv2 (256 -> 128)
    conv_mma_kernel<<<dim3(N / 64, CCH / 64), 128>>>(wc2, gh1, gh1, 2 * CCH, bc2, gh2, 2 * CCH, N, 0,
                                                     nullptr, nullptr, nullptr,
                                                     nullptr, nullptr, nullptr, 0);

    // 7) residual + tran_layer
    final_kernel<<<(N + 127) / 128, 128>>>(eigen, gh2, wt, bt, out, N);
}